// round 12
// baseline (speedup 1.0000x reference)
#include <cuda_runtime.h>
#include <cuda_fp16.h>
#include <mma.h>
#include <stdint.h>

using namespace nvcuda;

// Problem constants
#define BB     2
#define SQL    2048
#define SKVL   2048
#define DMODEL 1024
#define NH     16
#define HDIM   64
#define MQ     (BB*SQL)    // 4096
#define MKV    (BB*SKVL)   // 4096

// ---------------- scratch (device globals; no runtime allocation) ----------------
__device__ __half g_xq_h [MQ*DMODEL];
__device__ __half g_xkv_h[MKV*DMODEL];
__device__ __half g_wq_h [DMODEL*DMODEL];
__device__ __half g_wk_h [DMODEL*DMODEL];
__device__ __half g_wv_h [DMODEL*DMODEL];
__device__ __half g_wo_h [DMODEL*DMODEL];
__device__ __half g_qh   [MQ*DMODEL];   // [B,H,SQ,HD], pre-scaled by 1/8, rope applied
__device__ __half g_kh   [MKV*DMODEL];  // [B,H,SKV,HD], rope applied
__device__ __half g_vh   [MKV*DMODEL];  // [B,H,SKV,HD]
__device__ __half g_ctx_h[MQ*DMODEL];   // [B,SQ,D]

// ---------------- cp.async helpers ----------------
__device__ __forceinline__ void cp16(void* smem, const void* gmem) {
    uint32_t s = (uint32_t)__cvta_generic_to_shared(smem);
    asm volatile("cp.async.cg.shared.global [%0], [%1], 16;\n" :: "r"(s), "l"(gmem));
}
__device__ __forceinline__ void cp_commit() { asm volatile("cp.async.commit_group;\n"); }
template<int N> __device__ __forceinline__ void cp_wait() {
    asm volatile("cp.async.wait_group %0;\n" :: "n"(N));
}

// ---------------- fused fp32->fp16 convert (all 6 tensors, one launch) ----------------
__global__ void cvt_all(const float* __restrict__ xq, const float* __restrict__ xkv,
                        const float* __restrict__ wq, const float* __restrict__ wk,
                        const float* __restrict__ wv, const float* __restrict__ wo,
                        __half* oxq, __half* oxkv, __half* owq, __half* owk,
                        __half* owv, __half* owo) {
    int i = blockIdx.x * blockDim.x + threadIdx.x;   // float4 index, total 3M
    const float* src; __half* dst; int off;
    if (i < 1048576)      { src = xq;  dst = oxq;  off = i; }
    else if (i < 2097152) { src = xkv; dst = oxkv; off = i - 1048576; }
    else {
        int j = i - 2097152;
        int w = j >> 18;            // 0..3, 256K float4 each
        off = j & 262143;
        switch (w) {
            case 0: src = wq; dst = owq; break;
            case 1: src = wk; dst = owk; break;
            case 2: src = wv; dst = owv; break;
            default: src = wo; dst = owo; break;
        }
    }
    float4 v = reinterpret_cast<const float4*>(src)[off];
    reinterpret_cast<__half2*>(dst)[2*off]   = __floats2half2_rn(v.x, v.y);
    reinterpret_cast<__half2*>(dst)[2*off+1] = __floats2half2_rn(v.z, v.w);
}

// ---------------- WMMA GEMM mainloop: 4 warps, 64x64 warp tile, 3-stage cp.async ----------------
// C[128,128] tile of A[M,1024] * W[1024,1024]^T.  128 threads, warp layout 2x2.
#define GBM 128
#define GBN 128
#define GBK 32
#define GLD 40
#define GST_HALFS (GBM * GLD)              // one matrix, one stage: 5120 halfs
#define GSTAGE_BYTES (2 * GST_HALFS * 2)   // A+B one stage: 20480 B
#define GEMM_SMEM (3 * GSTAGE_BYTES)       // 61440 B
#define GTHREADS 128

// acc fragment layout (sm_80+ de-facto, m16n16k16 f32):
//   elem e: row = (lane>>2) + 8*((e>>1)&1), col = (lane&3)*2 + (e&1) + 8*(e>>2)

__device__ __forceinline__ void gemm_mainloop(
    const __half* __restrict__ A, const __half* __restrict__ Bm,
    char* dsm, int bm, int bn,
    wmma::fragment<wmma::accumulator, 16, 16, 16, float> (&acc)[4][4]) {

    const int K = DMODEL;
    int tid  = threadIdx.x;
    int warp = tid >> 5;
    int wm   = warp & 1;    // 0..1 -> 64 rows each
    int wn   = warp >> 1;   // 0..1 -> 64 cols each

    #pragma unroll
    for (int i = 0; i < 4; i++)
        #pragma unroll
        for (int j = 0; j < 4; j++)
            wmma::fill_fragment(acc[i][j], 0.0f);

    auto stA = [&](int st) { return (__half*)(dsm + st * GSTAGE_BYTES); };
    auto stB = [&](int st) { return (__half*)(dsm + st * GSTAGE_BYTES) + GST_HALFS; };

    int lrow = tid >> 2;          // 0..31
    int lcol = (tid & 3) * 8;     // 0,8,16,24

    auto load_stage = [&](int st, int kt) {
        int k0 = kt * GBK;
        __half* As = stA(st);
        __half* Bs = stB(st);
        #pragma unroll
        for (int p = 0; p < 4; p++) {
            int r = lrow + p * 32;
            cp16(As + r * GLD + lcol, A  + (size_t)(bm + r) * K + k0 + lcol);
            cp16(Bs + r * GLD + lcol, Bm + (size_t)(bn + r) * K + k0 + lcol);
        }
    };

    load_stage(0, 0); cp_commit();
    load_stage(1, 1); cp_commit();

    const int NK = K / GBK; // 32
    for (int kt = 0; kt < NK; kt++) {
        int st = kt % 3;
        if (kt == NK - 1) cp_wait<0>(); else cp_wait<1>();
        __syncthreads();
        if (kt + 2 < NK) { load_stage((kt + 2) % 3, kt + 2); cp_commit(); }

        __half* As = stA(st);
        __half* Bs = stB(st);
        #pragma unroll
        for (int kk = 0; kk < GBK; kk += 16) {
            wmma::fragment<wmma::matrix_a, 16, 16, 16, __half, wmma::row_major> af[4];
            wmma::fragment<wmma::matrix_b, 16, 16, 16, __half, wmma::col_major> bf[4];
            #pragma unroll
            for (int i = 0; i < 4; i++)
                wmma::load_matrix_sync(af[i], As + (wm * 64 + i * 16) * GLD + kk, GLD);
            #pragma unroll
            for (int j = 0; j < 4; j++)
                wmma::load_matrix_sync(bf[j], Bs + (wn * 64 + j * 16) * GLD + kk, GLD);
            #pragma unroll
            for (int i = 0; i < 4; i++)
                #pragma unroll
                for (int j = 0; j < 4; j++)
                    wmma::mma_sync(acc[i][j], af[i], bf[j], acc[i][j]);
        }
    }
}

// ---------------- combined Q/K/V projection kernel (grid.z selects) ----------------
// z=0: Q = x_q*wq^T + bq, rope, *0.125 -> g_qh
// z=1: K = x_kv*wk^T + bk, rope       -> g_kh
// z=2: V = x_kv*wv^T + bv             -> g_vh
__global__ __launch_bounds__(GTHREADS, 2)
void gemm_proj(const __half* __restrict__ xq, const __half* __restrict__ xkv,
               const __half* __restrict__ wq, const __half* __restrict__ wk,
               const __half* __restrict__ wv,
               const float* __restrict__ bq, const float* __restrict__ bk,
               const float* __restrict__ bv,
               __half* __restrict__ qh, __half* __restrict__ kh, __half* __restrict__ vh) {
    extern __shared__ char dsm[];
    int z = blockIdx.z;
    const __half* A  = (z == 0) ? xq : xkv;
    const __half* Bm = (z == 0) ? wq : (z == 1) ? wk : wv;
    const float* bias = (z == 0) ? bq : (z == 1) ? bk : bv;
    __half* Oh = (z == 0) ? qh : (z == 1) ? kh : vh;
    float scale = (z == 0) ? 0.125f : 1.0f;
    bool do_rope = (z < 2);

    int bm = blockIdx.y * GBM;
    int bn = blockIdx.x * GBN;

    wmma::fragment<wmma::accumulator, 16, 16, 16, float> acc[4][4];
    gemm_mainloop(A, Bm, dsm, bm, bn, acc);

    int lane = threadIdx.x & 31;
    int warp = threadIdx.x >> 5;
    int wm = warp & 1, wn = warp >> 1;

    #pragma unroll
    for (int i = 0; i < 4; i++) {
        #pragma unroll
        for (int j = 0; j < 4; j++) {
            int r0 = bm + wm * 64 + i * 16 + (lane >> 2);
            int c0 = bn + wn * 64 + j * 16 + (lane & 3) * 2;
            const float* x = acc[i][j].x;
            #pragma unroll
            for (int p = 0; p < 4; p++) {
                int row = r0 + ((p & 1) ? 8 : 0);
                int col = c0 + ((p & 2) ? 8 : 0);
                float xe = x[p * 2]     + bias[col];
                float xo = x[p * 2 + 1] + bias[col + 1];
                int head = col >> 6;
                int hd   = col & 63;
                int s    = row & (SQL - 1);
                int bi   = row >> 11;
                float re, ro;
                if (do_rope) {
                    int pr = hd >> 1;
                    float freq = expf(-(float)pr * (9.210340371976184f / 32.0f));
                    float ang  = (float)s * freq;
                    float cs = cosf(ang), sn = sinf(ang);
                    re = (xe * cs - xo * sn) * scale;
                    ro = (xe * sn + xo * cs) * scale;
                } else {
                    re = xe; ro = xo;
                }
                *(__half2*)(Oh + ((size_t)(bi * NH + head) * SQL + s) * HDIM + hd) =
                    __floats2half2_rn(re, ro);
            }
        }
    }
}

// ---------------- output projection kernel (f32 out + bias) ----------------
__global__ __launch_bounds__(GTHREADS, 2)
void gemm_out(const __half* __restrict__ A, const __half* __restrict__ Bm,
              const float* __restrict__ bias, float* __restrict__ C) {
    extern __shared__ char dsm[];
    int bm = blockIdx.y * GBM;
    int bn = blockIdx.x * GBN;

    wmma::fragment<wmma::accumulator, 16, 16, 16, float> acc[4][4];
    gemm_mainloop(A, Bm, dsm, bm, bn, acc);

    int lane = threadIdx.x & 31;
    int warp = threadIdx.x >> 5;
    int wm = warp & 1, wn = warp >> 1;
    const int N = DMODEL;

    #pragma unroll
    for (int i = 0; i < 4; i++) {
        #pragma unroll
        for (int j = 0; j < 4; j++) {
            int r0 = bm + wm * 64 + i * 16 + (lane >> 2);
            int c0 = bn + wn * 64 + j * 16 + (lane & 3) * 2;
            const float* x = acc[i][j].x;
            float2 v;
            v.x = x[0] + bias[c0];     v.y = x[1] + bias[c0 + 1];
            *(float2*)(C + (size_t)r0 * N + c0) = v;
            v.x = x[2] + bias[c0];     v.y = x[3] + bias[c0 + 1];
            *(float2*)(C + (size_t)(r0 + 8) * N + c0) = v;
            v.x = x[4] + bias[c0 + 8]; v.y = x[5] + bias[c0 + 9];
            *(float2*)(C + (size_t)r0 * N + c0 + 8) = v;
            v.x = x[6] + bias[c0 + 8]; v.y = x[7] + bias[c0 + 9];
            *(float2*)(C + (size_t)(r0 + 8) * N + c0 + 8) = v;
        }
    }
}

// ---------------- flash attention: 128-q tiles, 3-stage KV pipeline, 1 sync/iter ----------------
#define FQT  128
#define FKT  64
#define FLD  72
#define KVS  (FKT * FLD)   // one K or V stage, in halfs

#define FSMEM_BYTES ((FQT*FLD + 3*KVS + 3*KVS + FQT*FLD) * 2)   // 92160 B

__global__ __launch_bounds__(256)
void flash3(const __half* __restrict__ Q, const __half* __restrict__ K,
            const __half* __restrict__ V, __half* __restrict__ CTX) {
    extern __shared__ __half fsh[];
    __half* Qs = fsh;                 // FQT x FLD
    __half* Ks = Qs + FQT * FLD;      // 3 stages x FKT x FLD
    __half* Vs = Ks + 3 * KVS;        // 3 stages
    __half* Ps = Vs + 3 * KVS;        // FQT x FLD (per-warp private 16-row slices)

    int tid  = threadIdx.x;
    int lane = tid & 31;
    int warp = tid >> 5;
    int b    = blockIdx.z;
    int h    = blockIdx.y;
    int q0   = blockIdx.x * FQT;

    const __half* qptr  = Q + ((size_t)(b * NH + h) * SQL + q0) * HDIM;
    const __half* kbase = K + (size_t)(b * NH + h) * SKVL * HDIM;
    const __half* vbase = V + (size_t)(b * NH + h) * SKVL * HDIM;

    // load Q tile (128 x 64)
    for (int i = tid; i < FQT * 8; i += 256) {
        int r = i >> 3, c = (i & 7) * 8;
        *(float4*)(Qs + r * FLD + c) = *(const float4*)(qptr + r * HDIM + c);
    }

    auto copy_kv = [&](int st, int kt) {
        #pragma unroll
        for (int p = 0; p < 4; p++) {
            int i = tid + p * 256;
            int r = (i >> 3) & 63, c = (i & 7) * 8;
            if (i < 512)
                cp16(Ks + st * KVS + r * FLD + c, kbase + (size_t)(kt + r) * HDIM + c);
            else
                cp16(Vs + st * KVS + r * FLD + c, vbase + (size_t)(kt + r) * HDIM + c);
        }
    };

    copy_kv(0, 0); cp_commit();
    copy_kv(1, FKT); cp_commit();

    float m0 = -1e30f, m1 = -1e30f, l0 = 0.0f, l1 = 0.0f;

    wmma::fragment<wmma::accumulator, 16, 16, 16, float> O[4];
    #pragma unroll
    for (int j = 0; j < 4; j++) wmma::fill_fragment(O[j], 0.0f);

    int wrow = warp * 16;
    int cb   = (lane & 3) * 2;

    const int NT = SKVL / FKT;  // 32
    for (int t = 0; t < NT; t++) {
        int st = t % 3;
        if (t == NT - 1) cp_wait<0>(); else cp_wait<1>();
        __syncthreads();
        if (t + 2 < NT) { copy_kv((t + 2) % 3, (t + 2) * FKT); cp_commit(); }

        // ---- S = Q K^T (Q pre-scaled) ----
        wmma::fragment<wmma::accumulator, 16, 16, 16, float> S[4];
        #pragma unroll
        for (int j = 0; j < 4; j++) wmma::fill_fragment(S[j], 0.0f);
        #pragma unroll
        for (int kk = 0; kk < HDIM; kk += 16) {
            wmma::fragment<wmma::matrix_a, 16, 16, 16, __half, wmma::row_major> af;
            wmma::load_matrix_sync(af, Qs + wrow * FLD + kk, FLD);
            #pragma unroll
            for (int j = 0; j < 4; j++) {
                wmma::fragment<wmma::matrix_b, 16, 16, 16, __half, wmma::col_major> bf;
                wmma::load_matrix_sync(bf, Ks + st * KVS + (j * 16) * FLD + kk, FLD);
                wmma::mma_sync(S[j], af, bf, S[j]);
            }
        }

        // ---- online softmax in registers ----
        float mx0 = -1e30f, mx1 = -1e30f;
        #pragma unroll
        for (int j = 0; j < 4; j++) {
            const float* x = S[j].x;
            mx0 = fmaxf(mx0, fmaxf(fmaxf(x[0], x[1]), fmaxf(x[4], x[5])));
            mx1 = fmaxf(mx1, fmaxf(fmaxf(x[2], x[3]), fmaxf(x[6], x[7])));
        }
        mx0 = fmaxf(mx0, __shfl_xor_sync(0xffffffffu, mx0, 1));
        mx0 = fmaxf(mx0, __shfl_xor_sync(0xffffffffu, mx0, 2));
        mx1 = fmaxf(mx1, __shfl_xor_sync(0xffffffffu, mx1, 1));
        mx1 = fmaxf(mx1, __shfl_xor_sync(0xffffffffu, mx1, 2));

        float mn0 = fmaxf(m0, mx0), mn1 = fmaxf(m1, mx1);
        float a0  = __expf(m0 - mn0), a1 = __expf(m1 - mn1);

        __half* prow0 = Ps + (wrow + (lane >> 2)) * FLD;
        __half* prow1 = prow0 + 8 * FLD;
        float s0 = 0.0f, s1 = 0.0f;
        #pragma unroll
        for (int j = 0; j < 4; j++) {
            const float* x = S[j].x;
            int c = j * 16 + cb;
            float p0 = __expf(x[0] - mn0), p1 = __expf(x[1] - mn0);
            float p4 = __expf(x[4] - mn0), p5 = __expf(x[5] - mn0);
            float p2 = __expf(x[2] - mn1), p3 = __expf(x[3] - mn1);
            float p6 = __expf(x[6] - mn1), p7 = __expf(x[7] - mn1);
            s0 += p0 + p1 + p4 + p5;
            s1 += p2 + p3 + p6 + p7;
            *(__half2*)(prow0 + c)     = __floats2half2_rn(p0, p1);
            *(__half2*)(prow0 + c + 8) = __floats2half2_rn(p4, p5);
            *(__half2*)(prow1 + c)     = __floats2half2_rn(p2, p3);
            *(__half2*)(prow1 + c + 8) = __floats2half2_rn(p6, p7);
        }
        s0 += __shfl_xor_sync(0xffffffffu, s0, 1);
        s0 += __shfl_xor_sync(0xffffffffu, s0, 2);
        s1 += __shfl_xor_sync(0xffffffffu, s1, 1);
        s1 += __shfl_xor_sync(0xffffffffu, s1, 2);

        l0 = l0 * a0 + s0;  l1 = l1 * a1 + s1;
        m0 = mn0;           m1 = mn1;

        // rescale O accumulators by alpha (per fragment row)
        #pragma unroll
        for (int j = 0; j < 4; j++) {
            float* x = O[j].x;
            x[0] *= a0; x[1] *= a0; x[4] *= a0; x[5] *= a0;
            x[2] *= a1; x[3] *= a1; x[6] *= a1; x[7] *= a1;
        }
        __syncwarp();

        // ---- O += P V ----
        #pragma unroll
        for (int kk = 0; kk < 4; kk++) {
            wmma::fragment<wmma::matrix_a, 16, 16, 16, __half, wmma::row_major> af;
            wmma::load_matrix_sync(af, Ps + wrow * FLD + kk * 16, FLD);
            #pragma unroll
            for (int j = 0; j < 4; j++) {
                wmma::fragment<wmma::matrix_b, 16, 16, 16, __half, wmma::row_major> bf;
                wmma::load_matrix_sync(bf, Vs + st * KVS + (kk * 16) * FLD + j * 16, FLD);
                wmma::mma_sync(O[j], af, bf, O[j]);
            }
        }
    }

    // ---- epilogue: normalize + write ctx [B,SQ,D] half ----
    float il0 = 1.0f / l0, il1 = 1.0f / l1;
    int row0 = q0 + wrow + (lane >> 2);
    __half* o0 = CTX + (size_t)(b * SQL + row0) * DMODEL + h * HDIM + cb;
    __half* o1 = o0 + 8 * DMODEL;
    #pragma unroll
    for (int j = 0; j < 4; j++) {
        const float* x = O[j].x;
        int c = j * 16;
        *(__half2*)(o0 + c)     = __floats2half2_rn(x[0] * il0, x[1] * il0);
        *(__half2*)(o0 + c + 8) = __floats2half2_rn(x[4] * il0, x[5] * il0);
        *(__half2*)(o1 + c)     = __floats2half2_rn(x[2] * il1, x[3] * il1);
        *(__half2*)(o1 + c + 8) = __floats2half2_rn(x[6] * il1, x[7] * il1);
    }
}

// ---------------- host ----------------
extern "C" void kernel_launch(void* const* d_in, const int* in_sizes, int n_in,
                              void* d_out, int out_size) {
    const float* x_q  = (const float*)d_in[0];
    const float* x_kv = (const float*)d_in[1];
    const float* wq   = (const float*)d_in[2];
    const float* bq   = (const float*)d_in[3];
    const float* wk   = (const float*)d_in[4];
    const float* bk   = (const float*)d_in[5];
    const float* wv   = (const float*)d_in[6];
    const float* bv   = (const float*)d_in[7];
    const float* wo   = (const float*)d_in[8];
    const float* bo   = (const float*)d_in[9];
    float* out = (float*)d_out;

    void *p_xq, *p_xkv, *p_wq, *p_wk, *p_wv, *p_wo;
    void *p_qh, *p_kh, *p_vh, *p_ctx;
    cudaGetSymbolAddress(&p_xq,  g_xq_h);
    cudaGetSymbolAddress(&p_xkv, g_xkv_h);
    cudaGetSymbolAddress(&p_wq,  g_wq_h);
    cudaGetSymbolAddress(&p_wk,  g_wk_h);
    cudaGetSymbolAddress(&p_wv,  g_wv_h);
    cudaGetSymbolAddress(&p_wo,  g_wo_h);
    cudaGetSymbolAddress(&p_qh,  g_qh);
    cudaGetSymbolAddress(&p_kh,  g_kh);
    cudaGetSymbolAddress(&p_vh,  g_vh);
    cudaGetSymbolAddress(&p_ctx, g_ctx_h);

    cudaFuncSetAttribute(flash3,    cudaFuncAttributeMaxDynamicSharedMemorySize, FSMEM_BYTES);
    cudaFuncSetAttribute(gemm_proj, cudaFuncAttributeMaxDynamicSharedMemorySize, GEMM_SMEM);
    cudaFuncSetAttribute(gemm_out,  cudaFuncAttributeMaxDynamicSharedMemorySize, GEMM_SMEM);

    // one fused convert launch: 3M float4 chunks
    cvt_all<<<12288, 256>>>(x_q, x_kv, wq, wk, wv, wo,
                            (__half*)p_xq, (__half*)p_xkv, (__half*)p_wq,
                            (__half*)p_wk, (__half*)p_wv, (__half*)p_wo);

    // combined Q/K/V projections (bias + rope + relayout fused), one launch
    dim3 pgrid(DMODEL / GBN, MQ / GBM, 3);   // (8, 32, 3)
    gemm_proj<<<pgrid, GTHREADS, GEMM_SMEM>>>(
        (const __half*)p_xq, (const __half*)p_xkv,
        (const __half*)p_wq, (const __half*)p_wk, (const __half*)p_wv,
        bq, bk, bv,
        (__half*)p_qh, (__half*)p_kh, (__half*)p_vh);

    // flash attention
    dim3 fgrid(SQL / FQT, NH, BB);
    flash3<<<fgrid, 256, FSMEM_BYTES>>>((const __half*)p_qh, (const __half*)p_kh,
                                        (const __half*)p_vh, (__half*)p_ctx);

    // output projection (+bias fused)
    dim3 ogrid(DMODEL / GBN, MQ / GBM);
    gemm_out<<<ogrid, GTHREADS, GEMM_SMEM>>>((const __half*)p_ctx, (const __half*)p_wo, bo, out);
}

// round 13
// speedup vs baseline: 1.3397x; 1.3397x over previous
#include <cuda_runtime.h>
#include <cuda_fp16.h>
#include <mma.h>
#include <stdint.h>

using namespace nvcuda;

// Problem constants
#define BB     2
#define SQL    2048
#define SKVL   2048
#define DMODEL 1024
#define NH     16
#define HDIM   64
#define MQ     (BB*SQL)    // 4096
#define MKV    (BB*SKVL)   // 4096

// ---------------- scratch (device globals; no runtime allocation) ----------------
__device__ __half g_xq_h [MQ*DMODEL];
__device__ __half g_xkv_h[MKV*DMODEL];
__device__ __half g_wq_h [DMODEL*DMODEL];
__device__ __half g_wk_h [DMODEL*DMODEL];
__device__ __half g_wv_h [DMODEL*DMODEL];
__device__ __half g_wo_h [DMODEL*DMODEL];
__device__ __half g_qh   [MQ*DMODEL];   // [B,H,SQ,HD], pre-scaled by 1/8, rope applied
__device__ __half g_kh   [MKV*DMODEL];  // [B,H,SKV,HD], rope applied
__device__ __half g_vh   [MKV*DMODEL];  // [B,H,SKV,HD]
__device__ __half g_ctx_h[MQ*DMODEL];   // [B,SQ,D]

// ---------------- cp.async / mma / ldmatrix helpers ----------------
__device__ __forceinline__ void cp16(void* smem, const void* gmem) {
    uint32_t s = (uint32_t)__cvta_generic_to_shared(smem);
    asm volatile("cp.async.cg.shared.global [%0], [%1], 16;\n" :: "r"(s), "l"(gmem));
}
__device__ __forceinline__ void cp_commit() { asm volatile("cp.async.commit_group;\n"); }
template<int N> __device__ __forceinline__ void cp_wait() {
    asm volatile("cp.async.wait_group %0;\n" :: "n"(N));
}
__device__ __forceinline__ void ldsm_x4(uint32_t* r, uint32_t addr) {
    asm volatile("ldmatrix.sync.aligned.m8n8.x4.shared.b16 {%0,%1,%2,%3}, [%4];"
        : "=r"(r[0]), "=r"(r[1]), "=r"(r[2]), "=r"(r[3]) : "r"(addr));
}
__device__ __forceinline__ void ldsm_x4_t(uint32_t* r, uint32_t addr) {
    asm volatile("ldmatrix.sync.aligned.m8n8.x4.trans.shared.b16 {%0,%1,%2,%3}, [%4];"
        : "=r"(r[0]), "=r"(r[1]), "=r"(r[2]), "=r"(r[3]) : "r"(addr));
}
__device__ __forceinline__ void mma16816(float* c, const uint32_t* a, uint32_t b0, uint32_t b1) {
    asm volatile("mma.sync.aligned.m16n8k16.row.col.f32.f16.f16.f32 "
        "{%0,%1,%2,%3}, {%4,%5,%6,%7}, {%8,%9}, {%0,%1,%2,%3};"
        : "+f"(c[0]), "+f"(c[1]), "+f"(c[2]), "+f"(c[3])
        : "r"(a[0]), "r"(a[1]), "r"(a[2]), "r"(a[3]), "r"(b0), "r"(b1));
}
__device__ __forceinline__ uint32_t h2u(float a, float b) {
    __half2 h = __floats2half2_rn(a, b);
    return *reinterpret_cast<uint32_t*>(&h);
}

// ---------------- fused fp32->fp16 convert (all 6 tensors, one launch) ----------------
__global__ void cvt_all(const float* __restrict__ xq, const float* __restrict__ xkv,
                        const float* __restrict__ wq, const float* __restrict__ wk,
                        const float* __restrict__ wv, const float* __restrict__ wo,
                        __half* oxq, __half* oxkv, __half* owq, __half* owk,
                        __half* owv, __half* owo) {
    int i = blockIdx.x * blockDim.x + threadIdx.x;   // float4 index, total 3M
    const float* src; __half* dst; int off;
    if (i < 1048576)      { src = xq;  dst = oxq;  off = i; }
    else if (i < 2097152) { src = xkv; dst = oxkv; off = i - 1048576; }
    else {
        int j = i - 2097152;
        int w = j >> 18;
        off = j & 262143;
        switch (w) {
            case 0: src = wq; dst = owq; break;
            case 1: src = wk; dst = owk; break;
            case 2: src = wv; dst = owv; break;
            default: src = wo; dst = owo; break;
        }
    }
    float4 v = reinterpret_cast<const float4*>(src)[off];
    reinterpret_cast<__half2*>(dst)[2*off]   = __floats2half2_rn(v.x, v.y);
    reinterpret_cast<__half2*>(dst)[2*off+1] = __floats2half2_rn(v.z, v.w);
}

// ---------------- WMMA GEMM mainloop (R9 config: 8 warps, 32x64 warp tile) ----------------
#define GBM 128
#define GBN 128
#define GBK 32
#define GLD 40
#define GST_HALFS (GBM * GLD)
#define GSTAGE_BYTES (2 * GST_HALFS * 2)
#define GEMM_SMEM (3 * GSTAGE_BYTES)       // 61440 B
#define GTHREADS 256

__device__ __forceinline__ void gemm_mainloop(
    const __half* __restrict__ A, const __half* __restrict__ Bm,
    char* dsm, int bm, int bn,
    wmma::fragment<wmma::accumulator, 16, 16, 16, float> (&acc)[2][4]) {

    const int K = DMODEL;
    int tid  = threadIdx.x;
    int warp = tid >> 5;
    int wm   = warp & 3;
    int wn   = warp >> 2;

    #pragma unroll
    for (int i = 0; i < 2; i++)
        #pragma unroll
        for (int j = 0; j < 4; j++)
            wmma::fill_fragment(acc[i][j], 0.0f);

    auto stA = [&](int st) { return (__half*)(dsm + st * GSTAGE_BYTES); };
    auto stB = [&](int st) { return (__half*)(dsm + st * GSTAGE_BYTES) + GST_HALFS; };

    int lrow = tid >> 2;
    int lcol = (tid & 3) * 8;

    auto load_stage = [&](int st, int kt) {
        int k0 = kt * GBK;
        __half* As = stA(st);
        __half* Bs = stB(st);
        #pragma unroll
        for (int p = 0; p < 2; p++) {
            int r = lrow + p * 64;
            cp16(As + r * GLD + lcol, A  + (size_t)(bm + r) * K + k0 + lcol);
            cp16(Bs + r * GLD + lcol, Bm + (size_t)(bn + r) * K + k0 + lcol);
        }
    };

    load_stage(0, 0); cp_commit();
    load_stage(1, 1); cp_commit();

    const int NK = K / GBK; // 32
    for (int kt = 0; kt < NK; kt++) {
        int st = kt % 3;
        if (kt == NK - 1) cp_wait<0>(); else cp_wait<1>();
        __syncthreads();
        if (kt + 2 < NK) { load_stage((kt + 2) % 3, kt + 2); cp_commit(); }

        __half* As = stA(st);
        __half* Bs = stB(st);
        #pragma unroll
        for (int kk = 0; kk < GBK; kk += 16) {
            wmma::fragment<wmma::matrix_a, 16, 16, 16, __half, wmma::row_major> af[2];
            wmma::fragment<wmma::matrix_b, 16, 16, 16, __half, wmma::col_major> bf[4];
            #pragma unroll
            for (int i = 0; i < 2; i++)
                wmma::load_matrix_sync(af[i], As + (wm * 32 + i * 16) * GLD + kk, GLD);
            #pragma unroll
            for (int j = 0; j < 4; j++)
                wmma::load_matrix_sync(bf[j], Bs + (wn * 64 + j * 16) * GLD + kk, GLD);
            #pragma unroll
            for (int i = 0; i < 2; i++)
                #pragma unroll
                for (int j = 0; j < 4; j++)
                    wmma::mma_sync(acc[i][j], af[i], bf[j], acc[i][j]);
        }
    }
}

// ---------------- combined Q/K/V projection kernel (grid.z selects) ----------------
__global__ __launch_bounds__(GTHREADS, 2)
void gemm_proj(const __half* __restrict__ xq, const __half* __restrict__ xkv,
               const __half* __restrict__ wq, const __half* __restrict__ wk,
               const __half* __restrict__ wv,
               const float* __restrict__ bq, const float* __restrict__ bk,
               const float* __restrict__ bv,
               __half* __restrict__ qh, __half* __restrict__ kh, __half* __restrict__ vh) {
    extern __shared__ char dsm[];
    int z = blockIdx.z;
    const __half* A  = (z == 0) ? xq : xkv;
    const __half* Bm = (z == 0) ? wq : (z == 1) ? wk : wv;
    const float* bias = (z == 0) ? bq : (z == 1) ? bk : bv;
    __half* Oh = (z == 0) ? qh : (z == 1) ? kh : vh;
    float scale = (z == 0) ? 0.125f : 1.0f;
    bool do_rope = (z < 2);

    int bm = blockIdx.y * GBM;
    int bn = blockIdx.x * GBN;

    wmma::fragment<wmma::accumulator, 16, 16, 16, float> acc[2][4];
    gemm_mainloop(A, Bm, dsm, bm, bn, acc);

    int lane = threadIdx.x & 31;
    int warp = threadIdx.x >> 5;
    int wm = warp & 3, wn = warp >> 2;

    #pragma unroll
    for (int i = 0; i < 2; i++) {
        #pragma unroll
        for (int j = 0; j < 4; j++) {
            int r0 = bm + wm * 32 + i * 16 + (lane >> 2);
            int c0 = bn + wn * 64 + j * 16 + (lane & 3) * 2;
            const float* x = acc[i][j].x;
            #pragma unroll
            for (int p = 0; p < 4; p++) {
                int row = r0 + ((p & 1) ? 8 : 0);
                int col = c0 + ((p & 2) ? 8 : 0);
                float xe = x[p * 2]     + bias[col];
                float xo = x[p * 2 + 1] + bias[col + 1];
                int head = col >> 6;
                int hd   = col & 63;
                int s    = row & (SQL - 1);
                int bi   = row >> 11;
                float re, ro;
                if (do_rope) {
                    int pr = hd >> 1;
                    float freq = expf(-(float)pr * (9.210340371976184f / 32.0f));
                    float ang  = (float)s * freq;
                    float cs = cosf(ang), sn = sinf(ang);
                    re = (xe * cs - xo * sn) * scale;
                    ro = (xe * sn + xo * cs) * scale;
                } else {
                    re = xe; ro = xo;
                }
                *(__half2*)(Oh + ((size_t)(bi * NH + head) * SQL + s) * HDIM + hd) =
                    __floats2half2_rn(re, ro);
            }
        }
    }
}

// ---------------- output projection kernel (f32 out + bias) ----------------
__global__ __launch_bounds__(GTHREADS, 2)
void gemm_out(const __half* __restrict__ A, const __half* __restrict__ Bm,
              const float* __restrict__ bias, float* __restrict__ C) {
    extern __shared__ char dsm[];
    int bm = blockIdx.y * GBM;
    int bn = blockIdx.x * GBN;

    wmma::fragment<wmma::accumulator, 16, 16, 16, float> acc[2][4];
    gemm_mainloop(A, Bm, dsm, bm, bn, acc);

    int lane = threadIdx.x & 31;
    int warp = threadIdx.x >> 5;
    int wm = warp & 3, wn = warp >> 2;
    const int N = DMODEL;

    #pragma unroll
    for (int i = 0; i < 2; i++) {
        #pragma unroll
        for (int j = 0; j < 4; j++) {
            int r0 = bm + wm * 32 + i * 16 + (lane >> 2);
            int c0 = bn + wn * 64 + j * 16 + (lane & 3) * 2;
            const float* x = acc[i][j].x;
            float2 v;
            v.x = x[0] + bias[c0];     v.y = x[1] + bias[c0 + 1];
            *(float2*)(C + (size_t)r0 * N + c0) = v;
            v.x = x[2] + bias[c0];     v.y = x[3] + bias[c0 + 1];
            *(float2*)(C + (size_t)(r0 + 8) * N + c0) = v;
            v.x = x[4] + bias[c0 + 8]; v.y = x[5] + bias[c0 + 9];
            *(float2*)(C + (size_t)r0 * N + c0 + 8) = v;
            v.x = x[6] + bias[c0 + 8]; v.y = x[7] + bias[c0 + 9];
            *(float2*)(C + (size_t)(r0 + 8) * N + c0 + 8) = v;
        }
    }
}

// ---------------- flash attention v4: raw mma.sync, register-resident P ----------------
// 128-q tiles (8 warps x 16 rows), FKT=64 kv tiles, 3-stage cp.async.
// S acc layout (m16n8k16): tile j covers kv cols j*8..j*8+7.
//   thread: s0,s1 = (row g, col j*8+tig*2,+1); s2,s3 = (row g+8, same cols)
// This IS the m16n8k16 A-operand layout, so exp(S) packs straight into PV operands.
#define FQT  128
#define FKT  64
#define FLD  72
#define KVS  (FKT * FLD)   // one K or V stage, in halfs

#define FSMEM_BYTES ((FQT*FLD + 6*KVS) * 2)   // 73728 B (no P buffer)

__global__ __launch_bounds__(256, 2)
void flash4(const __half* __restrict__ Q, const __half* __restrict__ K,
            const __half* __restrict__ V, __half* __restrict__ CTX) {
    extern __shared__ __half fsh[];
    __half* Qs = fsh;                 // FQT x FLD
    __half* Ks = Qs + FQT * FLD;      // 3 stages x FKT x FLD
    __half* Vs = Ks + 3 * KVS;        // 3 stages

    int tid  = threadIdx.x;
    int lane = tid & 31;
    int warp = tid >> 5;
    int g    = lane >> 2;       // groupID (row within 8)
    int tig  = lane & 3;        // thread in group (col pair)
    int b    = blockIdx.z;
    int h    = blockIdx.y;
    int q0   = blockIdx.x * FQT;
    int wrow = warp * 16;

    const __half* qptr  = Q + ((size_t)(b * NH + h) * SQL + q0) * HDIM;
    const __half* kbase = K + (size_t)(b * NH + h) * SKVL * HDIM;
    const __half* vbase = V + (size_t)(b * NH + h) * SKVL * HDIM;

    // load Q tile (128 x 64)
    for (int i = tid; i < FQT * 8; i += 256) {
        int r = i >> 3, c = (i & 7) * 8;
        *(float4*)(Qs + r * FLD + c) = *(const float4*)(qptr + r * HDIM + c);
    }

    auto copy_kv = [&](int st, int kt) {
        #pragma unroll
        for (int p = 0; p < 4; p++) {
            int i = tid + p * 256;
            int r = (i >> 3) & 63, c = (i & 7) * 8;
            if (i < 512)
                cp16(Ks + st * KVS + r * FLD + c, kbase + (size_t)(kt + r) * HDIM + c);
            else
                cp16(Vs + st * KVS + r * FLD + c, vbase + (size_t)(kt + r) * HDIM + c);
        }
    };

    copy_kv(0, 0); cp_commit();
    copy_kv(1, FKT); cp_commit();
    __syncthreads();   // Q tile visible

    // per-lane ldmatrix address offsets (bytes)
    uint32_t qs_u  = (uint32_t)__cvta_generic_to_shared(Qs);
    uint32_t ks_u  = (uint32_t)__cvta_generic_to_shared(Ks);
    uint32_t vs_u  = (uint32_t)__cvta_generic_to_shared(Vs);
    // Q/V (x4 / x4.trans): row=(l&15), col_off=(l>>4)*8
    uint32_t offQV = (((uint32_t)(lane & 15)) * FLD + (uint32_t)(lane >> 4) * 8) * 2;
    // K (x4 non-trans B): row=(l&7)+((l>>4)&1)*8, col_off=((l>>3)&1)*8
    uint32_t offK  = ((((uint32_t)(lane & 7) + ((lane >> 4) & 1) * 8)) * FLD
                      + (uint32_t)((lane >> 3) & 1) * 8) * 2;

    // hoist Q fragments (A-operand) out of the KV loop: 4 kk-tiles x 4 regs
    uint32_t qa[4][4];
    #pragma unroll
    for (int kk = 0; kk < 4; kk++)
        ldsm_x4(qa[kk], qs_u + ((uint32_t)(wrow) * FLD + kk * 16) * 2 + offQV);

    float m0 = -1e30f, m1 = -1e30f, l0 = 0.0f, l1 = 0.0f;
    float O[8][4];
    #pragma unroll
    for (int j = 0; j < 8; j++)
        #pragma unroll
        for (int e = 0; e < 4; e++) O[j][e] = 0.0f;

    const int NT = SKVL / FKT;  // 32
    for (int t = 0; t < NT; t++) {
        int st = t % 3;
        if (t == NT - 1) cp_wait<0>(); else cp_wait<1>();
        __syncthreads();
        if (t + 2 < NT) { copy_kv((t + 2) % 3, (t + 2) * FKT); cp_commit(); }

        uint32_t kst = ks_u + (uint32_t)(st * KVS) * 2;
        uint32_t vst = vs_u + (uint32_t)(st * KVS) * 2;

        // ---- S = Q K^T ----
        float S[8][4];
        #pragma unroll
        for (int j = 0; j < 8; j++)
            #pragma unroll
            for (int e = 0; e < 4; e++) S[j][e] = 0.0f;

        #pragma unroll
        for (int kk = 0; kk < 4; kk++) {
            #pragma unroll
            for (int jp = 0; jp < 4; jp++) {
                uint32_t kb[4];
                ldsm_x4(kb, kst + ((uint32_t)(jp * 16) * FLD + kk * 16) * 2 + offK);
                mma16816(S[2*jp],   qa[kk], kb[0], kb[1]);
                mma16816(S[2*jp+1], qa[kk], kb[2], kb[3]);
            }
        }

        // ---- online softmax (register-resident) ----
        float mx0 = -1e30f, mx1 = -1e30f;
        #pragma unroll
        for (int j = 0; j < 8; j++) {
            mx0 = fmaxf(mx0, fmaxf(S[j][0], S[j][1]));
            mx1 = fmaxf(mx1, fmaxf(S[j][2], S[j][3]));
        }
        mx0 = fmaxf(mx0, __shfl_xor_sync(0xffffffffu, mx0, 1));
        mx0 = fmaxf(mx0, __shfl_xor_sync(0xffffffffu, mx0, 2));
        mx1 = fmaxf(mx1, __shfl_xor_sync(0xffffffffu, mx1, 1));
        mx1 = fmaxf(mx1, __shfl_xor_sync(0xffffffffu, mx1, 2));

        float mn0 = fmaxf(m0, mx0), mn1 = fmaxf(m1, mx1);
        float a0  = __expf(m0 - mn0), a1 = __expf(m1 - mn1);

        uint32_t PA[4][4];   // PV A-operands, packed from exp(S)
        float s0 = 0.0f, s1 = 0.0f;
        #pragma unroll
        for (int j = 0; j < 8; j++) {
            float e0 = __expf(S[j][0] - mn0), e1 = __expf(S[j][1] - mn0);
            float e2 = __expf(S[j][2] - mn1), e3 = __expf(S[j][3] - mn1);
            s0 += e0 + e1;  s1 += e2 + e3;
            int kk = j >> 1, hf = (j & 1) * 2;
            PA[kk][hf]     = h2u(e0, e1);
            PA[kk][hf + 1] = h2u(e2, e3);
        }
        s0 += __shfl_xor_sync(0xffffffffu, s0, 1);
        s0 += __shfl_xor_sync(0xffffffffu, s0, 2);
        s1 += __shfl_xor_sync(0xffffffffu, s1, 1);
        s1 += __shfl_xor_sync(0xffffffffu, s1, 2);

        l0 = l0 * a0 + s0;  l1 = l1 * a1 + s1;
        m0 = mn0;           m1 = mn1;

        #pragma unroll
        for (int j = 0; j < 8; j++) {
            O[j][0] *= a0; O[j][1] *= a0;
            O[j][2] *= a1; O[j][3] *= a1;
        }

        // ---- O += P V  (P in registers) ----
        #pragma unroll
        for (int kk = 0; kk < 4; kk++) {
            #pragma unroll
            for (int jp = 0; jp < 4; jp++) {
                uint32_t vb[4];
                ldsm_x4_t(vb, vst + ((uint32_t)(kk * 16) * FLD + jp * 16) * 2 + offQV);
                mma16816(O[2*jp],   PA[kk], vb[0], vb[1]);
                mma16816(O[2*jp+1], PA[kk], vb[2], vb[3]);
            }
        }
    }

    // ---- epilogue: normalize + write ctx [B,SQ,D] half ----
    float il0 = 1.0f / l0, il1 = 1.0f / l1;
    int r = q0 + wrow + g;
    __half* o0 = CTX + (size_t)(b * SQL + r) * DMODEL + h * HDIM + tig * 2;
    __half* o1 = o0 + 8 * DMODEL;
    #pragma unroll
    for (int j = 0; j < 8; j++) {
        __half2 v0 = __floats2half2_rn(O[j][0] * il0, O[j][1] * il0);
        __half2 v1 = __floats2half2_rn(O[j][2] * il1, O[j][3] * il1);
        *(__half2*)(o0 + j * 8) = v0;
        *(__half2*)(o1 + j * 8) = v1;
    }
}

// ---------------- host ----------------
extern "C" void kernel_launch(void* const* d_in, const int* in_sizes, int n_in,
                              void* d_out, int out_size) {
    const float* x_q  = (const float*)d_in[0];
    const float* x_kv = (const float*)d_in[1];
    const float* wq   = (const float*)d_in[2];
    const float* bq   = (const float*)d_in[3];
    const float* wk   = (const float*)d_in[4];
    const float* bk   = (const float*)d_in[5];
    const float* wv   = (const float*)d_in[6];
    const float* bv   = (const float*)d_in[7];
    const float* wo   = (const float*)d_in[8];
    const float* bo   = (const float*)d_in[9];
    float* out = (float*)d_out;

    void *p_xq, *p_xkv, *p_wq, *p_wk, *p_wv, *p_wo;
    void *p_qh, *p_kh, *p_vh, *p_ctx;
    cudaGetSymbolAddress(&p_xq,  g_xq_h);
    cudaGetSymbolAddress(&p_xkv, g_xkv_h);
    cudaGetSymbolAddress(&p_wq,  g_wq_h);
    cudaGetSymbolAddress(&p_wk,  g_wk_h);
    cudaGetSymbolAddress(&p_wv,  g_wv_h);
    cudaGetSymbolAddress(&p_wo,  g_wo_h);
    cudaGetSymbolAddress(&p_qh,  g_qh);
    cudaGetSymbolAddress(&p_kh,  g_kh);
    cudaGetSymbolAddress(&p_vh,  g_vh);
    cudaGetSymbolAddress(&p_ctx, g_ctx_h);

    cudaFuncSetAttribute(flash4,    cudaFuncAttributeMaxDynamicSharedMemorySize, FSMEM_BYTES);
    cudaFuncSetAttribute(gemm_proj, cudaFuncAttributeMaxDynamicSharedMemorySize, GEMM_SMEM);
    cudaFuncSetAttribute(gemm_out,  cudaFuncAttributeMaxDynamicSharedMemorySize, GEMM_SMEM);

    // one fused convert launch: 3M float4 chunks
    cvt_all<<<12288, 256>>>(x_q, x_kv, wq, wk, wv, wo,
                            (__half*)p_xq, (__half*)p_xkv, (__half*)p_wq,
                            (__half*)p_wk, (__half*)p_wv, (__half*)p_wo);

    // combined Q/K/V projections (bias + rope + relayout fused), one launch
    dim3 pgrid(DMODEL / GBN, MQ / GBM, 3);   // (8, 32, 3)
    gemm_proj<<<pgrid, GTHREADS, GEMM_SMEM>>>(
        (const __half*)p_xq, (const __half*)p_xkv,
        (const __half*)p_wq, (const __half*)p_wk, (const __half*)p_wv,
        bq, bk, bv,
        (__half*)p_qh, (__half*)p_kh, (__half*)p_vh);

    // flash attention
    dim3 fgrid(SQL / FQT, NH, BB);
    flash4<<<fgrid, 256, FSMEM_BYTES>>>((const __half*)p_qh, (const __half*)p_kh,
                                        (const __half*)p_vh, (__half*)p_ctx);

    // output projection (+bias fused)
    dim3 ogrid(DMODEL / GBN, MQ / GBM);
    gemm_out<<<ogrid, GTHREADS, GEMM_SMEM>>>((const __half*)p_ctx, (const __half*)p_wo, bo, out);
}

// round 14
// speedup vs baseline: 1.3858x; 1.0344x over previous
#include <cuda_runtime.h>
#include <cuda_fp16.h>
#include <stdint.h>

// Problem constants
#define BB     2
#define SQL    2048
#define SKVL   2048
#define DMODEL 1024
#define NH     16
#define HDIM   64
#define MQ     (BB*SQL)    // 4096
#define MKV    (BB*SKVL)   // 4096

// ---------------- scratch (device globals; no runtime allocation) ----------------
__device__ __half g_xq_h [MQ*DMODEL];
__device__ __half g_xkv_h[MKV*DMODEL];
__device__ __half g_wq_h [DMODEL*DMODEL];
__device__ __half g_wk_h [DMODEL*DMODEL];
__device__ __half g_wv_h [DMODEL*DMODEL];
__device__ __half g_wo_h [DMODEL*DMODEL];
__device__ __half g_qh   [MQ*DMODEL];   // [B,H,SQ,HD], pre-scaled by 1/8, rope applied
__device__ __half g_kh   [MKV*DMODEL];  // [B,H,SKV,HD], rope applied
__device__ __half g_vh   [MKV*DMODEL];  // [B,H,SKV,HD]
__device__ __half g_ctx_h[MQ*DMODEL];   // [B,SQ,D]

// ---------------- cp.async / mma / ldmatrix helpers ----------------
__device__ __forceinline__ void cp16(void* smem, const void* gmem) {
    uint32_t s = (uint32_t)__cvta_generic_to_shared(smem);
    asm volatile("cp.async.cg.shared.global [%0], [%1], 16;\n" :: "r"(s), "l"(gmem));
}
__device__ __forceinline__ void cp_commit() { asm volatile("cp.async.commit_group;\n"); }
template<int N> __device__ __forceinline__ void cp_wait() {
    asm volatile("cp.async.wait_group %0;\n" :: "n"(N));
}
__device__ __forceinline__ void ldsm_x4(uint32_t* r, uint32_t addr) {
    asm volatile("ldmatrix.sync.aligned.m8n8.x4.shared.b16 {%0,%1,%2,%3}, [%4];"
        : "=r"(r[0]), "=r"(r[1]), "=r"(r[2]), "=r"(r[3]) : "r"(addr));
}
__device__ __forceinline__ void ldsm_x4_t(uint32_t* r, uint32_t addr) {
    asm volatile("ldmatrix.sync.aligned.m8n8.x4.trans.shared.b16 {%0,%1,%2,%3}, [%4];"
        : "=r"(r[0]), "=r"(r[1]), "=r"(r[2]), "=r"(r[3]) : "r"(addr));
}
__device__ __forceinline__ void mma16816(float* c, const uint32_t* a, uint32_t b0, uint32_t b1) {
    asm volatile("mma.sync.aligned.m16n8k16.row.col.f32.f16.f16.f32 "
        "{%0,%1,%2,%3}, {%4,%5,%6,%7}, {%8,%9}, {%0,%1,%2,%3};"
        : "+f"(c[0]), "+f"(c[1]), "+f"(c[2]), "+f"(c[3])
        : "r"(a[0]), "r"(a[1]), "r"(a[2]), "r"(a[3]), "r"(b0), "r"(b1));
}
__device__ __forceinline__ uint32_t h2u(float a, float b) {
    __half2 h = __floats2half2_rn(a, b);
    return *reinterpret_cast<uint32_t*>(&h);
}

// ---------------- fused fp32->fp16 convert (all 6 tensors, one launch) ----------------
__global__ void cvt_all(const float* __restrict__ xq, const float* __restrict__ xkv,
                        const float* __restrict__ wq, const float* __restrict__ wk,
                        const float* __restrict__ wv, const float* __restrict__ wo,
                        __half* oxq, __half* oxkv, __half* owq, __half* owk,
                        __half* owv, __half* owo) {
    int i = blockIdx.x * blockDim.x + threadIdx.x;   // float4 index, total 3M
    const float* src; __half* dst; int off;
    if (i < 1048576)      { src = xq;  dst = oxq;  off = i; }
    else if (i < 2097152) { src = xkv; dst = oxkv; off = i - 1048576; }
    else {
        int j = i - 2097152;
        int w = j >> 18;
        off = j & 262143;
        switch (w) {
            case 0: src = wq; dst = owq; break;
            case 1: src = wk; dst = owk; break;
            case 2: src = wv; dst = owv; break;
            default: src = wo; dst = owo; break;
        }
    }
    float4 v = reinterpret_cast<const float4*>(src)[off];
    reinterpret_cast<__half2*>(dst)[2*off]   = __floats2half2_rn(v.x, v.y);
    reinterpret_cast<__half2*>(dst)[2*off+1] = __floats2half2_rn(v.z, v.w);
}

// ---------------- raw-mma GEMM mainloop: 8 warps, 32x64 warp tile, 3-stage cp.async ----------------
// C[128,128] tile of A[M,1024] * W[1024,1024]^T. 256 threads, warp layout 4x2.
// acc[i][j][e] (m16n8k16): i = m16 tile (wm*32+i*16), j = n8 tile (wn*64+j*8)
//   e0,e1 -> (row g,   col tig*2, tig*2+1);  e2,e3 -> (row g+8, same cols)
#define GBM 128
#define GBN 128
#define GBK 32
#define GLD 40
#define GST_HALFS (GBM * GLD)
#define GSTAGE_BYTES (2 * GST_HALFS * 2)
#define GEMM_SMEM (3 * GSTAGE_BYTES)       // 61440 B
#define GTHREADS 256

__device__ __forceinline__ void gemm_mainloop_raw(
    const __half* __restrict__ A, const __half* __restrict__ Bm,
    char* dsm, int bm, int bn, float (&acc)[2][8][4]) {

    const int K = DMODEL;
    int tid  = threadIdx.x;
    int lane = tid & 31;
    int warp = tid >> 5;
    int wm   = warp & 3;
    int wn   = warp >> 2;

    #pragma unroll
    for (int i = 0; i < 2; i++)
        #pragma unroll
        for (int j = 0; j < 8; j++)
            #pragma unroll
            for (int e = 0; e < 4; e++) acc[i][j][e] = 0.0f;

    uint32_t dsm_u = (uint32_t)__cvta_generic_to_shared(dsm);

    // ldmatrix lane-address offsets (bytes) — same patterns as flash4 (proven)
    uint32_t offA = (((uint32_t)(lane & 15)) * GLD + (uint32_t)(lane >> 4) * 8) * 2;
    uint32_t offB = ((((uint32_t)(lane & 7) + ((lane >> 4) & 1) * 8)) * GLD
                     + (uint32_t)((lane >> 3) & 1) * 8) * 2;

    int lrow = tid >> 2;
    int lcol = (tid & 3) * 8;

    auto load_stage = [&](int st, int kt) {
        int k0 = kt * GBK;
        __half* As = (__half*)(dsm + st * GSTAGE_BYTES);
        __half* Bs = As + GST_HALFS;
        #pragma unroll
        for (int p = 0; p < 2; p++) {
            int r = lrow + p * 64;
            cp16(As + r * GLD + lcol, A  + (size_t)(bm + r) * K + k0 + lcol);
            cp16(Bs + r * GLD + lcol, Bm + (size_t)(bn + r) * K + k0 + lcol);
        }
    };

    load_stage(0, 0); cp_commit();
    load_stage(1, 1); cp_commit();

    const int NK = K / GBK; // 32
    for (int kt = 0; kt < NK; kt++) {
        int st = kt % 3;
        if (kt == NK - 1) cp_wait<0>(); else cp_wait<1>();
        __syncthreads();
        if (kt + 2 < NK) { load_stage((kt + 2) % 3, kt + 2); cp_commit(); }

        uint32_t asb = dsm_u + st * GSTAGE_BYTES;
        uint32_t bsb = asb + GST_HALFS * 2;

        #pragma unroll
        for (int kk = 0; kk < GBK; kk += 16) {
            uint32_t a[2][4];
            #pragma unroll
            for (int i = 0; i < 2; i++)
                ldsm_x4(a[i], asb + ((uint32_t)(wm * 32 + i * 16) * GLD + kk) * 2 + offA);
            #pragma unroll
            for (int jt = 0; jt < 4; jt++) {
                uint32_t b[4];
                ldsm_x4(b, bsb + ((uint32_t)(wn * 64 + jt * 16) * GLD + kk) * 2 + offB);
                #pragma unroll
                for (int i = 0; i < 2; i++) {
                    mma16816(acc[i][jt * 2],     a[i], b[0], b[1]);
                    mma16816(acc[i][jt * 2 + 1], a[i], b[2], b[3]);
                }
            }
        }
    }
}

// ---------------- combined Q/K/V projection kernel (grid.z selects) ----------------
// z=0: Q = x_q*wq^T + bq, rope, *0.125 -> g_qh
// z=1: K = x_kv*wk^T + bk, rope       -> g_kh
// z=2: V = x_kv*wv^T + bv             -> g_vh
__global__ __launch_bounds__(GTHREADS, 2)
void gemm_proj(const __half* __restrict__ xq, const __half* __restrict__ xkv,
               const __half* __restrict__ wq, const __half* __restrict__ wk,
               const __half* __restrict__ wv,
               const float* __restrict__ bq, const float* __restrict__ bk,
               const float* __restrict__ bv,
               __half* __restrict__ qh, __half* __restrict__ kh, __half* __restrict__ vh) {
    extern __shared__ char dsm[];
    int z = blockIdx.z;
    const __half* A  = (z == 0) ? xq : xkv;
    const __half* Bm = (z == 0) ? wq : (z == 1) ? wk : wv;
    const float* bias = (z == 0) ? bq : (z == 1) ? bk : bv;
    __half* Oh = (z == 0) ? qh : (z == 1) ? kh : vh;
    float scale = (z == 0) ? 0.125f : 1.0f;
    bool do_rope = (z < 2);

    int bm = blockIdx.y * GBM;
    int bn = blockIdx.x * GBN;

    float acc[2][8][4];
    gemm_mainloop_raw(A, Bm, dsm, bm, bn, acc);

    int lane = threadIdx.x & 31;
    int warp = threadIdx.x >> 5;
    int wm = warp & 3, wn = warp >> 2;
    int g = lane >> 2, tig = lane & 3;

    #pragma unroll
    for (int i = 0; i < 2; i++) {
        int r0 = bm + wm * 32 + i * 16 + g;
        #pragma unroll
        for (int j = 0; j < 8; j++) {
            int c = bn + wn * 64 + j * 8 + tig * 2;
            const float* x = acc[i][j];
            int head = c >> 6;
            int hd   = c & 63;
            float be = bias[c], bo2 = bias[c + 1];
            #pragma unroll
            for (int p = 0; p < 2; p++) {
                int row = r0 + p * 8;
                float xe = x[p * 2]     + be;
                float xo = x[p * 2 + 1] + bo2;
                int s  = row & (SQL - 1);
                int bi = row >> 11;
                float re, ro;
                if (do_rope) {
                    int pr = hd >> 1;
                    float freq = expf(-(float)pr * (9.210340371976184f / 32.0f));
                    float ang  = (float)s * freq;
                    float cs = cosf(ang), sn = sinf(ang);
                    re = (xe * cs - xo * sn) * scale;
                    ro = (xe * sn + xo * cs) * scale;
                } else {
                    re = xe; ro = xo;
                }
                *(__half2*)(Oh + ((size_t)(bi * NH + head) * SQL + s) * HDIM + hd) =
                    __floats2half2_rn(re, ro);
            }
        }
    }
}

// ---------------- output projection kernel (f32 out + bias) ----------------
__global__ __launch_bounds__(GTHREADS, 2)
void gemm_out(const __half* __restrict__ A, const __half* __restrict__ Bm,
              const float* __restrict__ bias, float* __restrict__ C) {
    extern __shared__ char dsm[];
    int bm = blockIdx.y * GBM;
    int bn = blockIdx.x * GBN;

    float acc[2][8][4];
    gemm_mainloop_raw(A, Bm, dsm, bm, bn, acc);

    int lane = threadIdx.x & 31;
    int warp = threadIdx.x >> 5;
    int wm = warp & 3, wn = warp >> 2;
    int g = lane >> 2, tig = lane & 3;
    const int N = DMODEL;

    #pragma unroll
    for (int i = 0; i < 2; i++) {
        int r0 = bm + wm * 32 + i * 16 + g;
        #pragma unroll
        for (int j = 0; j < 8; j++) {
            int c = bn + wn * 64 + j * 8 + tig * 2;
            const float* x = acc[i][j];
            float be = bias[c], bo2 = bias[c + 1];
            float2 v0 = { x[0] + be, x[1] + bo2 };
            float2 v1 = { x[2] + be, x[3] + bo2 };
            *(float2*)(C + (size_t)r0 * N + c)       = v0;
            *(float2*)(C + (size_t)(r0 + 8) * N + c) = v1;
        }
    }
}

// ---------------- flash attention v4: raw mma.sync, register-resident P ----------------
#define FQT  128
#define FKT  64
#define FLD  72
#define KVS  (FKT * FLD)   // one K or V stage, in halfs

#define FSMEM_BYTES ((FQT*FLD + 6*KVS) * 2)   // 73728 B (no P buffer)

__global__ __launch_bounds__(256, 2)
void flash4(const __half* __restrict__ Q, const __half* __restrict__ K,
            const __half* __restrict__ V, __half* __restrict__ CTX) {
    extern __shared__ __half fsh[];
    __half* Qs = fsh;                 // FQT x FLD
    __half* Ks = Qs + FQT * FLD;      // 3 stages x FKT x FLD
    __half* Vs = Ks + 3 * KVS;        // 3 stages

    int tid  = threadIdx.x;
    int lane = tid & 31;
    int warp = tid >> 5;
    int g    = lane >> 2;
    int tig  = lane & 3;
    int b    = blockIdx.z;
    int h    = blockIdx.y;
    int q0   = blockIdx.x * FQT;
    int wrow = warp * 16;

    const __half* qptr  = Q + ((size_t)(b * NH + h) * SQL + q0) * HDIM;
    const __half* kbase = K + (size_t)(b * NH + h) * SKVL * HDIM;
    const __half* vbase = V + (size_t)(b * NH + h) * SKVL * HDIM;

    for (int i = tid; i < FQT * 8; i += 256) {
        int r = i >> 3, c = (i & 7) * 8;
        *(float4*)(Qs + r * FLD + c) = *(const float4*)(qptr + r * HDIM + c);
    }

    auto copy_kv = [&](int st, int kt) {
        #pragma unroll
        for (int p = 0; p < 4; p++) {
            int i = tid + p * 256;
            int r = (i >> 3) & 63, c = (i & 7) * 8;
            if (i < 512)
                cp16(Ks + st * KVS + r * FLD + c, kbase + (size_t)(kt + r) * HDIM + c);
            else
                cp16(Vs + st * KVS + r * FLD + c, vbase + (size_t)(kt + r) * HDIM + c);
        }
    };

    copy_kv(0, 0); cp_commit();
    copy_kv(1, FKT); cp_commit();
    __syncthreads();

    uint32_t qs_u  = (uint32_t)__cvta_generic_to_shared(Qs);
    uint32_t ks_u  = (uint32_t)__cvta_generic_to_shared(Ks);
    uint32_t vs_u  = (uint32_t)__cvta_generic_to_shared(Vs);
    uint32_t offQV = (((uint32_t)(lane & 15)) * FLD + (uint32_t)(lane >> 4) * 8) * 2;
    uint32_t offK  = ((((uint32_t)(lane & 7) + ((lane >> 4) & 1) * 8)) * FLD
                      + (uint32_t)((lane >> 3) & 1) * 8) * 2;

    uint32_t qa[4][4];
    #pragma unroll
    for (int kk = 0; kk < 4; kk++)
        ldsm_x4(qa[kk], qs_u + ((uint32_t)(wrow) * FLD + kk * 16) * 2 + offQV);

    float m0 = -1e30f, m1 = -1e30f, l0 = 0.0f, l1 = 0.0f;
    float O[8][4];
    #pragma unroll
    for (int j = 0; j < 8; j++)
        #pragma unroll
        for (int e = 0; e < 4; e++) O[j][e] = 0.0f;

    const int NT = SKVL / FKT;  // 32
    for (int t = 0; t < NT; t++) {
        int st = t % 3;
        if (t == NT - 1) cp_wait<0>(); else cp_wait<1>();
        __syncthreads();
        if (t + 2 < NT) { copy_kv((t + 2) % 3, (t + 2) * FKT); cp_commit(); }

        uint32_t kst = ks_u + (uint32_t)(st * KVS) * 2;
        uint32_t vst = vs_u + (uint32_t)(st * KVS) * 2;

        float S[8][4];
        #pragma unroll
        for (int j = 0; j < 8; j++)
            #pragma unroll
            for (int e = 0; e < 4; e++) S[j][e] = 0.0f;

        #pragma unroll
        for (int kk = 0; kk < 4; kk++) {
            #pragma unroll
            for (int jp = 0; jp < 4; jp++) {
                uint32_t kb[4];
                ldsm_x4(kb, kst + ((uint32_t)(jp * 16) * FLD + kk * 16) * 2 + offK);
                mma16816(S[2*jp],   qa[kk], kb[0], kb[1]);
                mma16816(S[2*jp+1], qa[kk], kb[2], kb[3]);
            }
        }

        float mx0 = -1e30f, mx1 = -1e30f;
        #pragma unroll
        for (int j = 0; j < 8; j++) {
            mx0 = fmaxf(mx0, fmaxf(S[j][0], S[j][1]));
            mx1 = fmaxf(mx1, fmaxf(S[j][2], S[j][3]));
        }
        mx0 = fmaxf(mx0, __shfl_xor_sync(0xffffffffu, mx0, 1));
        mx0 = fmaxf(mx0, __shfl_xor_sync(0xffffffffu, mx0, 2));
        mx1 = fmaxf(mx1, __shfl_xor_sync(0xffffffffu, mx1, 1));
        mx1 = fmaxf(mx1, __shfl_xor_sync(0xffffffffu, mx1, 2));

        float mn0 = fmaxf(m0, mx0), mn1 = fmaxf(m1, mx1);
        float a0  = __expf(m0 - mn0), a1 = __expf(m1 - mn1);

        uint32_t PA[4][4];
        float s0 = 0.0f, s1 = 0.0f;
        #pragma unroll
        for (int j = 0; j < 8; j++) {
            float e0 = __expf(S[j][0] - mn0), e1 = __expf(S[j][1] - mn0);
            float e2 = __expf(S[j][2] - mn1), e3 = __expf(S[j][3] - mn1);
            s0 += e0 + e1;  s1 += e2 + e3;
            int kk = j >> 1, hf = (j & 1) * 2;
            PA[kk][hf]     = h2u(e0, e1);
            PA[kk][hf + 1] = h2u(e2, e3);
        }
        s0 += __shfl_xor_sync(0xffffffffu, s0, 1);
        s0 += __shfl_xor_sync(0xffffffffu, s0, 2);
        s1 += __shfl_xor_sync(0xffffffffu, s1, 1);
        s1 += __shfl_xor_sync(0xffffffffu, s1, 2);

        l0 = l0 * a0 + s0;  l1 = l1 * a1 + s1;
        m0 = mn0;           m1 = mn1;

        #pragma unroll
        for (int j = 0; j < 8; j++) {
            O[j][0] *= a0; O[j][1] *= a0;
            O[j][2] *= a1; O[j][3] *= a1;
        }

        #pragma unroll
        for (int kk = 0; kk < 4; kk++) {
            #pragma unroll
            for (int jp = 0; jp < 4; jp++) {
                uint32_t vb[4];
                ldsm_x4_t(vb, vst + ((uint32_t)(kk * 16) * FLD + jp * 16) * 2 + offQV);
                mma16816(O[2*jp],   PA[kk], vb[0], vb[1]);
                mma16816(O[2*jp+1], PA[kk], vb[2], vb[3]);
            }
        }
    }

    float il0 = 1.0f / l0, il1 = 1.0f / l1;
    int r = q0 + wrow + g;
    __half* o0 = CTX + (size_t)(b * SQL + r) * DMODEL + h * HDIM + tig * 2;
    __half* o1 = o0 + 8 * DMODEL;
    #pragma unroll
    for (int j = 0; j < 8; j++) {
        __half2 v0 = __floats2half2_rn(O[j][0] * il0, O[j][1] * il0);
        __half2 v1 = __floats2half2_rn(O[j][2] * il1, O[j][3] * il1);
        *(__half2*)(o0 + j * 8) = v0;
        *(__half2*)(o1 + j * 8) = v1;
    }
}

// ---------------- host ----------------
extern "C" void kernel_launch(void* const* d_in, const int* in_sizes, int n_in,
                              void* d_out, int out_size) {
    const float* x_q  = (const float*)d_in[0];
    const float* x_kv = (const float*)d_in[1];
    const float* wq   = (const float*)d_in[2];
    const float* bq   = (const float*)d_in[3];
    const float* wk   = (const float*)d_in[4];
    const float* bk   = (const float*)d_in[5];
    const float* wv   = (const float*)d_in[6];
    const float* bv   = (const float*)d_in[7];
    const float* wo   = (const float*)d_in[8];
    const float* bo   = (const float*)d_in[9];
    float* out = (float*)d_out;

    void *p_xq, *p_xkv, *p_wq, *p_wk, *p_wv, *p_wo;
    void *p_qh, *p_kh, *p_vh, *p_ctx;
    cudaGetSymbolAddress(&p_xq,  g_xq_h);
    cudaGetSymbolAddress(&p_xkv, g_xkv_h);
    cudaGetSymbolAddress(&p_wq,  g_wq_h);
    cudaGetSymbolAddress(&p_wk,  g_wk_h);
    cudaGetSymbolAddress(&p_wv,  g_wv_h);
    cudaGetSymbolAddress(&p_wo,  g_wo_h);
    cudaGetSymbolAddress(&p_qh,  g_qh);
    cudaGetSymbolAddress(&p_kh,  g_kh);
    cudaGetSymbolAddress(&p_vh,  g_vh);
    cudaGetSymbolAddress(&p_ctx, g_ctx_h);

    cudaFuncSetAttribute(flash4,    cudaFuncAttributeMaxDynamicSharedMemorySize, FSMEM_BYTES);
    cudaFuncSetAttribute(gemm_proj, cudaFuncAttributeMaxDynamicSharedMemorySize, GEMM_SMEM);
    cudaFuncSetAttribute(gemm_out,  cudaFuncAttributeMaxDynamicSharedMemorySize, GEMM_SMEM);

    // one fused convert launch: 3M float4 chunks
    cvt_all<<<12288, 256>>>(x_q, x_kv, wq, wk, wv, wo,
                            (__half*)p_xq, (__half*)p_xkv, (__half*)p_wq,
                            (__half*)p_wk, (__half*)p_wv, (__half*)p_wo);

    // combined Q/K/V projections (bias + rope + relayout fused), one launch
    dim3 pgrid(DMODEL / GBN, MQ / GBM, 3);   // (8, 32, 3)
    gemm_proj<<<pgrid, GTHREADS, GEMM_SMEM>>>(
        (const __half*)p_xq, (const __half*)p_xkv,
        (const __half*)p_wq, (const __half*)p_wk, (const __half*)p_wv,
        bq, bk, bv,
        (__half*)p_qh, (__half*)p_kh, (__half*)p_vh);

    // flash attention
    dim3 fgrid(SQL / FQT, NH, BB);
    flash4<<<fgrid, 256, FSMEM_BYTES>>>((const __half*)p_qh, (const __half*)p_kh,
                                        (const __half*)p_vh, (__half*)p_ctx);

    // output projection (+bias fused)
    dim3 ogrid(DMODEL / GBN, MQ / GBM);
    gemm_out<<<ogrid, GTHREADS, GEMM_SMEM>>>((const __half*)p_ctx, (const __half*)p_wo, bo, out);
}